// round 16
// baseline (speedup 1.0000x reference)
#include <cuda_runtime.h>
#include <cstdint>

#define B_  32
#define T_  2048
#define IN_ 512
#define H_  256
#define NG  32      // groups of 8 presynaptic neurons
#define NP  256     // patterns per group (2^8)
#define NCH 32      // T_/64 proj chunks per batch

#define NSCAN 32    // scan CTAs (one per batch)
#define NWORK 116   // persistent GEMM worker CTAs
#define NJOBS 2048  // (B_*T_/GM) * 2 n-halves

// Scratch (allocation-free rule: __device__ globals)
__device__ float g_proj[(size_t)B_ * T_ * H_];        // 64 MB input projection
__device__ float g_Vt[H_ * H_];                       // Vt[j][h] = V[h][j]
__device__ float g_tab[(size_t)NG * NP * H_];         // 8 MB group subset-sum table
__device__ unsigned g_flag[B_ * NCH];                 // producer->consumer chunk flags

// ---------------------------------------------------------------------------
// Setup kernels
// ---------------------------------------------------------------------------
__global__ void transpose_V(const float* __restrict__ V) {
    int j = blockIdx.x;
    int h = threadIdx.x;
    g_Vt[j * H_ + h] = V[h * H_ + j];
}

// tab[g][p][h] = sum_{i: bit i of p} Vt[8g+i][h]   (ascending i)
__global__ void build_tab(void) {
    const int blk = blockIdx.x;          // 0..8191
    const int g = blk >> 8;
    const int p = blk & 255;
    const int h = threadIdx.x;
    float s = 0.0f;
    #pragma unroll
    for (int i = 0; i < 8; i++)
        if ((p >> i) & 1)
            s = __fadd_rn(s, g_Vt[(g * 8 + i) * H_ + h]);
    g_tab[((size_t)g * NP + p) * H_ + h] = s;
}

__global__ void init_flags(void) {
    g_flag[threadIdx.x] = 0u;
}

// ---------------------------------------------------------------------------
// chunk-ready spin (acquire)
// ---------------------------------------------------------------------------
__device__ __forceinline__ void wait_chunk(const unsigned* f) {
    unsigned v;
    do {
        asm volatile("ld.acquire.gpu.global.u32 %0, [%1];"
                     : "=r"(v) : "l"(f) : "memory");
    } while (v < 2u);
}

// ---------------------------------------------------------------------------
// Fused persistent kernel.
//   CTA 0..31   : LIF scan (pair-halves gather, shfl combine, ONE barrier)
//   CTA 32..147 : GEMM workers, grid-stride over NJOBS tile jobs
// ---------------------------------------------------------------------------
#define GM 64
#define GN 128
#define GK 16

__global__ __launch_bounds__(256, 1) void fused_kernel(
    const float* __restrict__ x, const float* __restrict__ W,
    const float* __restrict__ bia,
    const float* __restrict__ b_rec, float* __restrict__ out) {

    __shared__ float As[2][GK][GM];       // GEMM buffers (worker role)
    __shared__ float Bs[2][GK][GN];
    __shared__ unsigned sbits[2][8];      // [buf][warp] ballot words (scan role)

    const int cta = blockIdx.x;
    const int tid = threadIdx.x;

    if (cta >= NSCAN) {
        // =================== GEMM worker role (R15-identical) ===================
        const int tx = tid & 15;
        const int ty = tid >> 4;
        const int lr = tid >> 2;
        const int lc = (tid & 3) * 4;

        for (int jj = cta - NSCAN; jj < NJOBS; jj += NWORK) {
            const int nt = jj & 1;
            const int b  = (jj >> 1) & 31;
            const int tc = jj >> 6;
            const size_t m0 = (size_t)b * T_ + (size_t)tc * GM;
            const int bn = nt * GN;

            float acc[4][8];
            #pragma unroll
            for (int i = 0; i < 4; i++)
                #pragma unroll
                for (int j = 0; j < 8; j++) acc[i][j] = 0.0f;

            float4 ra, rb0, rb1;
            ra  = *(const float4*)&x[(m0 + lr) * IN_ + lc];
            rb0 = *(const float4*)&W[(size_t)(bn + lr) * IN_ + lc];
            rb1 = *(const float4*)&W[(size_t)(bn + 64 + lr) * IN_ + lc];
            As[0][lc + 0][lr] = ra.x;  As[0][lc + 1][lr] = ra.y;
            As[0][lc + 2][lr] = ra.z;  As[0][lc + 3][lr] = ra.w;
            Bs[0][lc + 0][lr] = rb0.x; Bs[0][lc + 1][lr] = rb0.y;
            Bs[0][lc + 2][lr] = rb0.z; Bs[0][lc + 3][lr] = rb0.w;
            Bs[0][lc + 0][lr + 64] = rb1.x; Bs[0][lc + 1][lr + 64] = rb1.y;
            Bs[0][lc + 2][lr + 64] = rb1.z; Bs[0][lc + 3][lr + 64] = rb1.w;
            __syncthreads();

            const int NT = IN_ / GK;   // 32
            for (int kt = 0; kt < NT; kt++) {
                const int cur = kt & 1, nxt = cur ^ 1;
                if (kt + 1 < NT) {
                    int k0 = (kt + 1) * GK + lc;
                    ra  = *(const float4*)&x[(m0 + lr) * IN_ + k0];
                    rb0 = *(const float4*)&W[(size_t)(bn + lr) * IN_ + k0];
                    rb1 = *(const float4*)&W[(size_t)(bn + 64 + lr) * IN_ + k0];
                }
                #pragma unroll
                for (int kk = 0; kk < GK; kk++) {
                    float a[4], bb[8];
                    *(float4*)&a[0]  = *(const float4*)&As[cur][kk][ty * 4];
                    *(float4*)&bb[0] = *(const float4*)&Bs[cur][kk][tx * 8];
                    *(float4*)&bb[4] = *(const float4*)&Bs[cur][kk][tx * 8 + 4];
                    #pragma unroll
                    for (int i = 0; i < 4; i++)
                        #pragma unroll
                        for (int j = 0; j < 8; j++)
                            acc[i][j] = fmaf(a[i], bb[j], acc[i][j]);
                }
                if (kt + 1 < NT) {
                    As[nxt][lc + 0][lr] = ra.x;  As[nxt][lc + 1][lr] = ra.y;
                    As[nxt][lc + 2][lr] = ra.z;  As[nxt][lc + 3][lr] = ra.w;
                    Bs[nxt][lc + 0][lr] = rb0.x; Bs[nxt][lc + 1][lr] = rb0.y;
                    Bs[nxt][lc + 2][lr] = rb0.z; Bs[nxt][lc + 3][lr] = rb0.w;
                    Bs[nxt][lc + 0][lr + 64] = rb1.x; Bs[nxt][lc + 1][lr + 64] = rb1.y;
                    Bs[nxt][lc + 2][lr + 64] = rb1.z; Bs[nxt][lc + 3][lr + 64] = rb1.w;
                }
                __syncthreads();
            }

            float bv[8];
            #pragma unroll
            for (int j = 0; j < 8; j++) bv[j] = bia[bn + tx * 8 + j];
            #pragma unroll
            for (int i = 0; i < 4; i++) {
                size_t m = m0 + ty * 4 + i;
                float4 o0, o1;
                o0.x = acc[i][0] + bv[0]; o0.y = acc[i][1] + bv[1];
                o0.z = acc[i][2] + bv[2]; o0.w = acc[i][3] + bv[3];
                o1.x = acc[i][4] + bv[4]; o1.y = acc[i][5] + bv[5];
                o1.z = acc[i][6] + bv[6]; o1.w = acc[i][7] + bv[7];
                *(float4*)&g_proj[m * H_ + bn + tx * 8]     = o0;
                *(float4*)&g_proj[m * H_ + bn + tx * 8 + 4] = o1;
            }

            __syncthreads();
            if (tid == 0) {
                __threadfence();
                atomicAdd(&g_flag[b * NCH + tc], 1u);
            }
        }
        return;
    }

    // ============ scan role (pair-halves gather, shfl combine) ============
    // Thread tid: pair hp = tid>>1, half h2 = tid&1 (even lanes half 0).
    // Half 0 gathers groups 0..15 (= quarters 0,1), half 1 groups 16..31
    // (= quarters 2,3) for its h-pair: 16 unconditional LDG.64, front-
    // batched. Local serial-ascending sums give s01 / s23; shfl_xor(1)
    // exchanges them in-warp. Thread then owns neuron h = tid for LIF.
    // Addition tree bitwise identical to R7/R15.
    const int b = cta;
    const int h = tid;
    const int wid = tid >> 5, lane = tid & 31;
    const int hp = tid >> 1, h2 = tid & 1;

    const float* pb = g_proj + (size_t)b * T_ * H_;
    float* ob = out + (size_t)b * T_ * H_;
    const float brec = b_rec[h];
    const unsigned* fb = g_flag + b * NCH;

    // table byte base: this half's 16 groups start at group 16*h2; h-pair offset
    const char* tbase = (const char*)g_tab
                      + ((size_t)h2 * 16 * NP * H_ * 4)
                      + (size_t)hp * 8;

    if (tid < 8) sbits[0][tid] = 0u;
    __syncthreads();

    if (tid == 0) wait_chunk(fb);
    __syncthreads();

    float mem = 0.0f, spk = 0.0f;
    int buf = 0;
    float p0 = pb[h];
    float p1 = pb[H_ + h];

    for (int t = 0; t < T_; t++) {
        const int tn = t + 2;
        if (tn < T_ && (tn & 63) == 0) {
            if (tid == 0) wait_chunk(fb + (tn >> 6));
            __syncthreads();
        }
        float p2 = (tn < T_) ? pb[(size_t)tn * H_ + h] : 0.0f;

        // ---- pattern words for this half's 16 groups (one LDS.128) ----
        const uint4 uu = ((const uint4*)&sbits[buf][0])[h2];
        const unsigned wd[4] = {uu.x, uu.y, uu.z, uu.w};

        // ---- 16 unconditional LDG.64, loads first, adds after ----
        float2 v[16];
        #pragma unroll
        for (int i = 0; i < 16; i++) {
            const unsigned pat = (wd[i >> 2] >> ((i & 3) * 8)) & 0xFFu;
            v[i] = __ldg((const float2*)(tbase + (((unsigned)i << 8) + pat) * 1024u));
        }
        // serial ascending within each 8-group quarter (bitwise = R7)
        float2 aA = make_float2(0.f, 0.f);
        float2 aB = make_float2(0.f, 0.f);
        #pragma unroll
        for (int i = 0; i < 8; i++) {
            aA.x = __fadd_rn(aA.x, v[i].x);
            aA.y = __fadd_rn(aA.y, v[i].y);
            aB.x = __fadd_rn(aB.x, v[8 + i].x);
            aB.y = __fadd_rn(aB.y, v[8 + i].y);
        }
        // s = q0+q1 (half 0)  or  q2+q3 (half 1)
        const float sx = __fadd_rn(aA.x, aB.x);
        const float sy = __fadd_rn(aA.y, aB.y);

        // ---- in-warp combine: exchange with partner lane (lane^1) ----
        const float ox = __shfl_xor_sync(0xFFFFFFFFu, sx, 1);
        const float oy = __shfl_xor_sync(0xFFFFFFFFu, sy, 1);
        // neuron h = 2*hp + h2 -> component = h2; (q0+q1)+(q2+q3) either way
        float rec = h2 ? __fadd_rn(oy, sy) : __fadd_rn(sx, ox);
        rec = __fadd_rn(rec, brec);

        // ---- LIF update (bitwise-identical rounding order) ----
        const float reset = (mem > 1.0f) ? 1.0f : 0.0f;
        const float in_ = __fadd_rn(p0, spk);
        mem = __fsub_rn(__fadd_rn(__fadd_rn(__fmul_rn(0.85f, mem), in_), rec), reset);
        const float s = (mem > 1.0f) ? 1.0f : 0.0f;
        ob[(size_t)t * H_ + h] = s;

        // ---- publish spikes; single barrier per step ----
        const unsigned ball = __ballot_sync(0xFFFFFFFFu, s != 0.0f);
        const int nb = buf ^ 1;
        if (lane == 0) sbits[nb][wid] = ball;
        __syncthreads();

        buf = nb; spk = s;
        p0 = p1; p1 = p2;
    }
}

// ---------------------------------------------------------------------------
extern "C" void kernel_launch(void* const* d_in, const int* in_sizes, int n_in,
                              void* d_out, int out_size) {
    const float* x     = (const float*)d_in[0];
    const float* W_in  = (const float*)d_in[1];
    const float* b_in  = (const float*)d_in[2];
    const float* V     = (const float*)d_in[3];
    const float* b_rec = (const float*)d_in[4];
    float* out = (float*)d_out;

    transpose_V<<<H_, H_>>>(V);
    build_tab<<<NG * NP, H_>>>();
    init_flags<<<1, B_ * NCH>>>();
    fused_kernel<<<NSCAN + NWORK, 256>>>(x, W_in, b_in, b_rec, out);
}